// round 1
// baseline (speedup 1.0000x reference)
#include <cuda_runtime.h>

#define BATCH 4
#define S 1024
#define D 1024
#define H 16
#define DK 64

typedef unsigned long long u64;

__device__ __forceinline__ u64 pack2(float lo, float hi) {
    u64 r; asm("mov.b64 %0, {%1, %2};" : "=l"(r) : "f"(lo), "f"(hi)); return r;
}
__device__ __forceinline__ void unpack2(u64 v, float& lo, float& hi) {
    asm("mov.b64 {%0, %1}, %2;" : "=f"(lo), "=f"(hi) : "l"(v));
}
__device__ __forceinline__ u64 ffma2(u64 a, u64 b, u64 c) {
    u64 d; asm("fma.rn.f32x2 %0, %1, %2, %3;" : "=l"(d) : "l"(a), "l"(b), "l"(c)); return d;
}

// scratch (allocation-free: __device__ globals)
__device__ float g_q[BATCH * S * D];      // projected Q, layout [b*s][h*dk+d]
__device__ float g_k[BATCH * S * D];      // projected K, same layout
__device__ float g_asco[BATCH * H * S];   // aspect_scores [b*h][j]

// ---------------------------------------------------------------------------
// Kernel 1: C = X @ W^T + bias  (M=4096, N=1024, K=1024), z=0 -> Q, z=1 -> K
// 128x128 tile, BK=16, 8x8 per-thread micro tile, packed f32x2 FMAs.
// ---------------------------------------------------------------------------
__global__ __launch_bounds__(256) void proj_kernel(
    const float* __restrict__ Xq, const float* __restrict__ Wq, const float* __restrict__ bq,
    const float* __restrict__ Xk, const float* __restrict__ Wk, const float* __restrict__ bk)
{
    const bool is_k = blockIdx.z != 0;
    const float* __restrict__ X = is_k ? Xk : Xq;
    const float* __restrict__ W = is_k ? Wk : Wq;
    const float* __restrict__ bias = is_k ? bk : bq;
    float* __restrict__ C = is_k ? g_k : g_q;

    __shared__ float as[16][128];   // [k][m]
    __shared__ float bs[16][128];   // [k][n]

    const int tid = threadIdx.x;
    const int tx = tid & 15;        // col group  (cols tx*8 .. +7)
    const int ty = tid >> 4;        // row group  (rows ty*8 .. +7)
    const int m0 = blockIdx.x * 128;
    const int n0 = blockIdx.y * 128;

    u64 acc[8][4];
#pragma unroll
    for (int r = 0; r < 8; r++)
#pragma unroll
        for (int c = 0; c < 4; c++) acc[r][c] = 0ull;

    for (int k0 = 0; k0 < D; k0 += 16) {
        __syncthreads();
#pragma unroll
        for (int i = 0; i < 2; i++) {
            int idx = tid + i * 256;
            int m = idx & 127;
            int kq = (idx >> 7) << 2;      // 0,4,8,12
            float4 v = *(const float4*)(X + (size_t)(m0 + m) * D + k0 + kq);
            as[kq + 0][m] = v.x; as[kq + 1][m] = v.y;
            as[kq + 2][m] = v.z; as[kq + 3][m] = v.w;
            float4 w = *(const float4*)(W + (size_t)(n0 + m) * D + k0 + kq);
            bs[kq + 0][m] = w.x; bs[kq + 1][m] = w.y;
            bs[kq + 2][m] = w.z; bs[kq + 3][m] = w.w;
        }
        __syncthreads();
#pragma unroll
        for (int kk = 0; kk < 16; kk++) {
            ulonglong2 b01 = *(const ulonglong2*)&bs[kk][tx * 8];
            ulonglong2 b23 = *(const ulonglong2*)&bs[kk][tx * 8 + 4];
            float4 a0 = *(const float4*)&as[kk][ty * 8];
            float4 a1 = *(const float4*)&as[kk][ty * 8 + 4];
            float av[8] = {a0.x, a0.y, a0.z, a0.w, a1.x, a1.y, a1.z, a1.w};
#pragma unroll
            for (int r = 0; r < 8; r++) {
                u64 asp = pack2(av[r], av[r]);
                acc[r][0] = ffma2(asp, b01.x, acc[r][0]);
                acc[r][1] = ffma2(asp, b01.y, acc[r][1]);
                acc[r][2] = ffma2(asp, b23.x, acc[r][2]);
                acc[r][3] = ffma2(asp, b23.y, acc[r][3]);
            }
        }
    }

    float bv[8];
    {
        float4 v0 = *(const float4*)(bias + n0 + tx * 8);
        float4 v1 = *(const float4*)(bias + n0 + tx * 8 + 4);
        bv[0] = v0.x; bv[1] = v0.y; bv[2] = v0.z; bv[3] = v0.w;
        bv[4] = v1.x; bv[5] = v1.y; bv[6] = v1.z; bv[7] = v1.w;
    }
#pragma unroll
    for (int r = 0; r < 8; r++) {
        float s[8];
#pragma unroll
        for (int c = 0; c < 4; c++) unpack2(acc[r][c], s[2 * c], s[2 * c + 1]);
        float* dst = C + (size_t)(m0 + ty * 8 + r) * D + n0 + tx * 8;
        float4 o0 = make_float4(s[0] + bv[0], s[1] + bv[1], s[2] + bv[2], s[3] + bv[3]);
        float4 o1 = make_float4(s[4] + bv[4], s[5] + bv[5], s[6] + bv[6], s[7] + bv[7]);
        *(float4*)dst = o0;
        *(float4*)(dst + 4) = o1;
    }
}

// ---------------------------------------------------------------------------
// Kernel 2: aspect path.  grid = B*H blocks of 256 threads.
// asp = aspect @ Wd^T + bd ; aw = asp @ weight_m[h] ;
// asco[j] = tanh(aw . k[b,h,j,:] + bias_m)
// ---------------------------------------------------------------------------
__global__ __launch_bounds__(256) void aspect_kernel(
    const float* __restrict__ aspect, const float* __restrict__ Wd, const float* __restrict__ bd,
    const float* __restrict__ wm, const float* __restrict__ bm)
{
    const int bh = blockIdx.x;
    const int b = bh >> 4;
    const int h = bh & 15;
    const int tid = threadIdx.x;

    __shared__ float asp_s[64];
    __shared__ float aw_s[64];

    {
        int e = tid >> 2, p = tid & 3;
        const float* av = aspect + (size_t)b * D + p * 256;
        const float* wv = Wd + (size_t)e * D + p * 256;
        float sum = 0.f;
#pragma unroll 4
        for (int d = 0; d < 256; d += 4) {
            float4 a = *(const float4*)(av + d);
            float4 w = *(const float4*)(wv + d);
            sum += a.x * w.x + a.y * w.y + a.z * w.z + a.w * w.w;
        }
        sum += __shfl_xor_sync(0xffffffffu, sum, 1, 4);
        sum += __shfl_xor_sync(0xffffffffu, sum, 2, 4);
        if (p == 0) asp_s[e] = sum + bd[e];
    }
    __syncthreads();
    if (tid < 64) {
        float s = 0.f;
        const float* w = wm + (size_t)h * DK * DK + tid;
#pragma unroll 8
        for (int c = 0; c < 64; c++) s += asp_s[c] * w[c * 64];
        aw_s[tid] = s;
    }
    __syncthreads();
    const float bias = bm[0];
    for (int j = tid; j < S; j += 256) {
        const float* kr = g_k + ((size_t)b * S + j) * D + h * DK;
        float s = 0.f;
#pragma unroll
        for (int d = 0; d < 64; d += 4) {
            float4 kv = *(const float4*)(kr + d);
            s += aw_s[d] * kv.x + aw_s[d + 1] * kv.y + aw_s[d + 2] * kv.z + aw_s[d + 3] * kv.w;
        }
        // accurate tanh: 1 - 2/(exp(2x)+1); __expf rel err ~2^-22
        float x = s + bias;
        float t = 1.f - 2.f / (__expf(2.f * x) + 1.f);
        g_asco[(size_t)bh * S + j] = t;
    }
}

// ---------------------------------------------------------------------------
// Kernel 3: fused scores + epilogue + softmax.
// One CTA = (b, h, 16 q-rows) x all 1024 keys held in registers (64 acc/thread
// as 32 f32x2). K streamed through smem in 8-dk chunks. Epilogue fuses
// /8 + aspect + short + mask, two-level row max/sum, normalized write.
// ---------------------------------------------------------------------------
__global__ __launch_bounds__(256) void scores_kernel(
    const float* __restrict__ shortp, const int* __restrict__ mask, float* __restrict__ out)
{
    const int b = blockIdx.z;
    const int h = blockIdx.y;
    const int m0 = blockIdx.x * 16;
    const int tid = threadIdx.x;
    const int ty = tid >> 7;       // 0..1   (rows ty*8 .. +7)
    const int tx = tid & 127;      // 0..127 (cols tx*8 .. +7)
    const int bh = b * H + h;

    __shared__ float qs[64][16];     // [dk][m]
    __shared__ float ks[8][1024];    // [dk-chunk][j]
    __shared__ float ascs[1024];
    __shared__ float red_m[2][4][8];
    __shared__ float red_s[2][4][8];

    {
        int m = tid & 15, kq = tid >> 4;   // kq 0..15
        float4 v = *(const float4*)(g_q + ((size_t)b * S + m0 + m) * D + h * DK + kq * 4);
        qs[kq * 4 + 0][m] = v.x; qs[kq * 4 + 1][m] = v.y;
        qs[kq * 4 + 2][m] = v.z; qs[kq * 4 + 3][m] = v.w;
    }
#pragma unroll
    for (int i = 0; i < 4; i++) {
        int j = tid + i * 256;
        ascs[j] = g_asco[(size_t)bh * S + j];
    }

    u64 acc[8][4];
#pragma unroll
    for (int r = 0; r < 8; r++)
#pragma unroll
        for (int c = 0; c < 4; c++) acc[r][c] = 0ull;

    for (int d0 = 0; d0 < DK; d0 += 8) {
        __syncthreads();
#pragma unroll
        for (int i = 0; i < 4; i++) {
            int j = tid + i * 256;
            const float* kr = g_k + ((size_t)b * S + j) * D + h * DK + d0;
            float4 v0 = *(const float4*)kr;
            float4 v1 = *(const float4*)(kr + 4);
            ks[0][j] = v0.x; ks[1][j] = v0.y; ks[2][j] = v0.z; ks[3][j] = v0.w;
            ks[4][j] = v1.x; ks[5][j] = v1.y; ks[6][j] = v1.z; ks[7][j] = v1.w;
        }
        __syncthreads();
#pragma unroll
        for (int kk = 0; kk < 8; kk++) {
            ulonglong2 k01 = *(const ulonglong2*)&ks[kk][tx * 8];
            ulonglong2 k23 = *(const ulonglong2*)&ks[kk][tx * 8 + 4];
            float4 q0 = *(const float4*)&qs[d0 + kk][ty * 8];
            float4 q1 = *(const float4*)&qs[d0 + kk][ty * 8 + 4];
            float qv[8] = {q0.x, q0.y, q0.z, q0.w, q1.x, q1.y, q1.z, q1.w};
#pragma unroll
            for (int r = 0; r < 8; r++) {
                u64 qsp = pack2(qv[r], qv[r]);
                acc[r][0] = ffma2(qsp, k01.x, acc[r][0]);
                acc[r][1] = ffma2(qsp, k01.y, acc[r][1]);
                acc[r][2] = ffma2(qsp, k23.x, acc[r][2]);
                acc[r][3] = ffma2(qsp, k23.y, acc[r][3]);
            }
        }
    }

    // ---- epilogue: s = acc/8 + asco[col] + short; mask; softmax over cols ----
    const int wg = (tid >> 5) & 3;
    const int lane = tid & 31;
    float rmax[8];

    float4 a0 = *(const float4*)&ascs[tx * 8];
    float4 a1 = *(const float4*)&ascs[tx * 8 + 4];

#pragma unroll
    for (int r = 0; r < 8; r++) {
        const int row = m0 + ty * 8 + r;
        const float* sh = shortp + ((size_t)bh * S + row) * S + tx * 8;
        float4 s0 = *(const float4*)sh;
        float4 s1 = *(const float4*)(sh + 4);
        const int* mp = mask + ((size_t)b * S + row) * S + tx * 8;
        int4 mk0 = *(const int4*)mp;
        int4 mk1 = *(const int4*)(mp + 4);
        float sc[8];
#pragma unroll
        for (int c = 0; c < 4; c++) unpack2(acc[r][c], sc[2 * c], sc[2 * c + 1]);
        sc[0] = sc[0] * 0.125f + a0.x + s0.x;
        sc[1] = sc[1] * 0.125f + a0.y + s0.y;
        sc[2] = sc[2] * 0.125f + a0.z + s0.z;
        sc[3] = sc[3] * 0.125f + a0.w + s0.w;
        sc[4] = sc[4] * 0.125f + a1.x + s1.x;
        sc[5] = sc[5] * 0.125f + a1.y + s1.y;
        sc[6] = sc[6] * 0.125f + a1.z + s1.z;
        sc[7] = sc[7] * 0.125f + a1.w + s1.w;
        if (mk0.x == 0) sc[0] = -1e9f;
        if (mk0.y == 0) sc[1] = -1e9f;
        if (mk0.z == 0) sc[2] = -1e9f;
        if (mk0.w == 0) sc[3] = -1e9f;
        if (mk1.x == 0) sc[4] = -1e9f;
        if (mk1.y == 0) sc[5] = -1e9f;
        if (mk1.z == 0) sc[6] = -1e9f;
        if (mk1.w == 0) sc[7] = -1e9f;
        float m01 = fmaxf(sc[0], sc[1]), m23 = fmaxf(sc[2], sc[3]);
        float m45 = fmaxf(sc[4], sc[5]), m67 = fmaxf(sc[6], sc[7]);
        rmax[r] = fmaxf(fmaxf(m01, m23), fmaxf(m45, m67));
#pragma unroll
        for (int c = 0; c < 4; c++) acc[r][c] = pack2(sc[2 * c], sc[2 * c + 1]);
    }
#pragma unroll
    for (int r = 0; r < 8; r++) {
        float m = rmax[r];
#pragma unroll
        for (int off = 16; off > 0; off >>= 1)
            m = fmaxf(m, __shfl_xor_sync(0xffffffffu, m, off));
        rmax[r] = m;
    }
    if (lane == 0) {
#pragma unroll
        for (int r = 0; r < 8; r++) red_m[ty][wg][r] = rmax[r];
    }
    __syncthreads();
    float rsum[8];
#pragma unroll
    for (int r = 0; r < 8; r++) {
        float m = fmaxf(fmaxf(red_m[ty][0][r], red_m[ty][1][r]),
                        fmaxf(red_m[ty][2][r], red_m[ty][3][r]));
        float sum = 0.f;
#pragma unroll
        for (int c = 0; c < 4; c++) {
            float e0, e1;
            unpack2(acc[r][c], e0, e1);
            e0 = __expf(e0 - m);
            e1 = __expf(e1 - m);
            sum += e0 + e1;
            acc[r][c] = pack2(e0, e1);
        }
        rsum[r] = sum;
    }
#pragma unroll
    for (int r = 0; r < 8; r++) {
        float sm = rsum[r];
#pragma unroll
        for (int off = 16; off > 0; off >>= 1)
            sm += __shfl_xor_sync(0xffffffffu, sm, off);
        rsum[r] = sm;
    }
    if (lane == 0) {
#pragma unroll
        for (int r = 0; r < 8; r++) red_s[ty][wg][r] = rsum[r];
    }
    __syncthreads();
#pragma unroll
    for (int r = 0; r < 8; r++) {
        float total = red_s[ty][0][r] + red_s[ty][1][r] + red_s[ty][2][r] + red_s[ty][3][r];
        float inv = 1.0f / total;
        const int row = m0 + ty * 8 + r;
        float* dst = out + ((size_t)bh * S + row) * S + tx * 8;
        float o[8];
#pragma unroll
        for (int c = 0; c < 4; c++) unpack2(acc[r][c], o[2 * c], o[2 * c + 1]);
        float4 o0 = make_float4(o[0] * inv, o[1] * inv, o[2] * inv, o[3] * inv);
        float4 o1 = make_float4(o[4] * inv, o[5] * inv, o[6] * inv, o[7] * inv);
        *(float4*)dst = o0;
        *(float4*)(dst + 4) = o1;
    }
}

// ---------------------------------------------------------------------------
extern "C" void kernel_launch(void* const* d_in, const int* in_sizes, int n_in,
                              void* d_out, int out_size)
{
    const float* query  = (const float*)d_in[0];
    const float* key    = (const float*)d_in[1];
    const int*   mask   = (const int*)  d_in[2];
    const float* aspect = (const float*)d_in[3];
    const float* shortp = (const float*)d_in[4];
    const float* Wq     = (const float*)d_in[5];
    const float* bq     = (const float*)d_in[6];
    const float* Wk     = (const float*)d_in[7];
    const float* bk     = (const float*)d_in[8];
    const float* Wd     = (const float*)d_in[9];
    const float* bd     = (const float*)d_in[10];
    const float* wm     = (const float*)d_in[11];
    const float* bm     = (const float*)d_in[12];
    float* out = (float*)d_out;

    dim3 gp(32, 8, 2);                 // M tiles, N tiles, {Q,K}
    proj_kernel<<<gp, 256>>>(query, Wq, bq, key, Wk, bk);

    aspect_kernel<<<BATCH * H, 256>>>(aspect, Wd, bd, wm, bm);

    dim3 gs(S / 16, H, BATCH);
    scores_kernel<<<gs, 256>>>(shortp, mask, out);
}

// round 3
// speedup vs baseline: 2.4102x; 2.4102x over previous
#include <cuda_runtime.h>
#include <cuda_bf16.h>

#define BATCH 4
#define S 1024
#define D 1024
#define H 16
#define DK 64

// ---------------------------------------------------------------------------
// scratch (allocation-free: __device__ globals)
// Q/K are stored as split bf16: value ~= hi + lo, each bf16. 8MB per array.
// ---------------------------------------------------------------------------
__device__ __nv_bfloat16 g_q_hi[BATCH * S * D];
__device__ __nv_bfloat16 g_q_lo[BATCH * S * D];
__device__ __nv_bfloat16 g_k_hi[BATCH * S * D];
__device__ __nv_bfloat16 g_k_lo[BATCH * S * D];
__device__ float g_asco[BATCH * H * S];

// ---------------------------------------------------------------------------
// helpers
// ---------------------------------------------------------------------------
__device__ __forceinline__ unsigned sm_u32(const void* p) {
    return (unsigned)__cvta_generic_to_shared(p);
}

__device__ __forceinline__ void ldsm4(unsigned r[4], unsigned addr) {
    asm volatile("ldmatrix.sync.aligned.m8n8.x4.shared.b16 {%0,%1,%2,%3}, [%4];"
                 : "=r"(r[0]), "=r"(r[1]), "=r"(r[2]), "=r"(r[3])
                 : "r"(addr));
}

__device__ __forceinline__ void mma16816(float* c, const unsigned* a, const unsigned* b) {
    asm volatile(
        "mma.sync.aligned.m16n8k16.row.col.f32.bf16.bf16.f32 "
        "{%0,%1,%2,%3}, {%4,%5,%6,%7}, {%8,%9}, {%0,%1,%2,%3};"
        : "+f"(c[0]), "+f"(c[1]), "+f"(c[2]), "+f"(c[3])
        : "r"(a[0]), "r"(a[1]), "r"(a[2]), "r"(a[3]), "r"(b[0]), "r"(b[1]));
}

// split (x,y) into packed bf16x2 hi and lo: x ~= hi.x + lo.x
__device__ __forceinline__ void split_pack(float x, float y, unsigned& hi, unsigned& lo) {
    __nv_bfloat162 h, l;
    h.x = __float2bfloat16(x);
    h.y = __float2bfloat16(y);
    l.x = __float2bfloat16(x - __bfloat162float(h.x));
    l.y = __float2bfloat16(y - __bfloat162float(h.y));
    hi = *reinterpret_cast<unsigned*>(&h);
    lo = *reinterpret_cast<unsigned*>(&l);
}

// ---------------------------------------------------------------------------
// Kernel 1: C = X @ W^T + bias  (M=4096, N=1024, K=1024), z in {Q, K}.
// 128x128 CTA tile, BK=32, double-buffered smem, split-bf16 mma (3 products).
// ---------------------------------------------------------------------------
#define PJ_AHI 0
#define PJ_ALO 10240
#define PJ_BHI 20480
#define PJ_BLO 30720
#define PJ_BUF 40960

__global__ void __launch_bounds__(256, 1) proj_kernel(
    const float* __restrict__ Xq, const float* __restrict__ Wq, const float* __restrict__ bq,
    const float* __restrict__ Xk, const float* __restrict__ Wk, const float* __restrict__ bk)
{
    extern __shared__ char smem_raw[];
    const bool is_k = blockIdx.z != 0;
    const float* __restrict__ X = is_k ? Xk : Xq;
    const float* __restrict__ W = is_k ? Wk : Wq;
    const float* __restrict__ bias = is_k ? bk : bq;
    __nv_bfloat16* __restrict__ Chi = is_k ? g_k_hi : g_q_hi;
    __nv_bfloat16* __restrict__ Clo = is_k ? g_k_lo : g_q_lo;

    const int tid = threadIdx.x;
    const int lane = tid & 31;
    const int wid = tid >> 5;
    const int wm = wid & 3;          // warp row group: rows wm*32..+31
    const int wn = wid >> 2;         // warp col group: cols wn*64..+63
    const int m0 = blockIdx.x * 128;
    const int n0 = blockIdx.y * 128;

    const unsigned sbase = sm_u32(smem_raw);

    float acc[2][8][4];
#pragma unroll
    for (int mt = 0; mt < 2; mt++)
#pragma unroll
        for (int nt = 0; nt < 8; nt++)
#pragma unroll
            for (int i = 0; i < 4; i++) acc[mt][nt][i] = 0.f;

    float4 ra[4], rb[4];

    // ---- load chunk 0 into regs ----
#pragma unroll
    for (int l = 0; l < 4; l++) {
        int f = tid + l * 256;
        int row = f >> 3, c4 = f & 7;
        ra[l] = *(const float4*)(X + (size_t)(m0 + row) * D + c4 * 4);
        rb[l] = *(const float4*)(W + (size_t)(n0 + row) * D + c4 * 4);
    }
    // store to buffer 0
#pragma unroll
    for (int l = 0; l < 4; l++) {
        int f = tid + l * 256;
        int row = f >> 3, c4 = f & 7;
        unsigned h0, l0, h1, l1;
        split_pack(ra[l].x, ra[l].y, h0, l0);
        split_pack(ra[l].z, ra[l].w, h1, l1);
        *(uint2*)(smem_raw + PJ_AHI + row * 80 + c4 * 8) = make_uint2(h0, h1);
        *(uint2*)(smem_raw + PJ_ALO + row * 80 + c4 * 8) = make_uint2(l0, l1);
        split_pack(rb[l].x, rb[l].y, h0, l0);
        split_pack(rb[l].z, rb[l].w, h1, l1);
        *(uint2*)(smem_raw + PJ_BHI + row * 80 + c4 * 8) = make_uint2(h0, h1);
        *(uint2*)(smem_raw + PJ_BLO + row * 80 + c4 * 8) = make_uint2(l0, l1);
    }
    __syncthreads();

    for (int c = 0; c < 32; c++) {
        // prefetch next chunk into regs
        if (c < 31) {
            int k0 = (c + 1) * 32;
#pragma unroll
            for (int l = 0; l < 4; l++) {
                int f = tid + l * 256;
                int row = f >> 3, c4 = f & 7;
                ra[l] = *(const float4*)(X + (size_t)(m0 + row) * D + k0 + c4 * 4);
                rb[l] = *(const float4*)(W + (size_t)(n0 + row) * D + k0 + c4 * 4);
            }
        }
        // compute on buffer c&1
        {
            const unsigned base = sbase + (c & 1) * PJ_BUF;
#pragma unroll
            for (int kk = 0; kk < 2; kk++) {
                unsigned ahi[2][4], alo[2][4];
#pragma unroll
                for (int mt = 0; mt < 2; mt++) {
                    unsigned rbytes = (unsigned)(wm * 32 + mt * 16 + (lane & 7) + ((lane >> 3) & 1) * 8) * 80
                                    + ((lane >> 4) & 1) * 16 + kk * 32;
                    ldsm4(ahi[mt], base + PJ_AHI + rbytes);
                    ldsm4(alo[mt], base + PJ_ALO + rbytes);
                }
#pragma unroll
                for (int nt2 = 0; nt2 < 4; nt2++) {
                    unsigned rbytes = (unsigned)(wn * 64 + nt2 * 16 + (lane & 7) + ((lane >> 4) & 1) * 8) * 80
                                    + ((lane >> 3) & 1) * 16 + kk * 32;
                    unsigned bhi[4], blo[4];
                    ldsm4(bhi, base + PJ_BHI + rbytes);
                    ldsm4(blo, base + PJ_BLO + rbytes);
#pragma unroll
                    for (int mt = 0; mt < 2; mt++) {
                        mma16816(acc[mt][nt2 * 2],     ahi[mt], bhi);
                        mma16816(acc[mt][nt2 * 2 + 1], ahi[mt], bhi + 2);
                        mma16816(acc[mt][nt2 * 2],     ahi[mt], blo);
                        mma16816(acc[mt][nt2 * 2 + 1], ahi[mt], blo + 2);
                        mma16816(acc[mt][nt2 * 2],     alo[mt], bhi);
                        mma16816(acc[mt][nt2 * 2 + 1], alo[mt], bhi + 2);
                    }
                }
            }
        }
        // store prefetched chunk to other buffer
        if (c < 31) {
            char* dst = smem_raw + ((c + 1) & 1) * PJ_BUF;
#pragma unroll
            for (int l = 0; l < 4; l++) {
                int f = tid + l * 256;
                int row = f >> 3, c4 = f & 7;
                unsigned h0, l0, h1, l1;
                split_pack(ra[l].x, ra[l].y, h0, l0);
                split_pack(ra[l].z, ra[l].w, h1, l1);
                *(uint2*)(dst + PJ_AHI + row * 80 + c4 * 8) = make_uint2(h0, h1);
                *(uint2*)(dst + PJ_ALO + row * 80 + c4 * 8) = make_uint2(l0, l1);
                split_pack(rb[l].x, rb[l].y, h0, l0);
                split_pack(rb[l].z, rb[l].w, h1, l1);
                *(uint2*)(dst + PJ_BHI + row * 80 + c4 * 8) = make_uint2(h0, h1);
                *(uint2*)(dst + PJ_BLO + row * 80 + c4 * 8) = make_uint2(l0, l1);
            }
            __syncthreads();
        }
    }

    // ---- epilogue: bias add, split to hi/lo bf16, store ----
    const int q = lane >> 2, tig = lane & 3;
#pragma unroll
    for (int mt = 0; mt < 2; mt++) {
#pragma unroll
        for (int nt = 0; nt < 8; nt++) {
            int col = n0 + wn * 64 + nt * 8 + tig * 2;
            float2 bb = *(const float2*)(bias + col);
            int row = m0 + wm * 32 + mt * 16 + q;
            unsigned hi, lo;
            split_pack(acc[mt][nt][0] + bb.x, acc[mt][nt][1] + bb.y, hi, lo);
            *reinterpret_cast<unsigned*>(&Chi[(size_t)row * D + col]) = hi;
            *reinterpret_cast<unsigned*>(&Clo[(size_t)row * D + col]) = lo;
            split_pack(acc[mt][nt][2] + bb.x, acc[mt][nt][3] + bb.y, hi, lo);
            *reinterpret_cast<unsigned*>(&Chi[(size_t)(row + 8) * D + col]) = hi;
            *reinterpret_cast<unsigned*>(&Clo[(size_t)(row + 8) * D + col]) = lo;
        }
    }
}

// ---------------------------------------------------------------------------
// Kernel 2: aspect path (K read from split bf16).
// ---------------------------------------------------------------------------
__global__ __launch_bounds__(256) void aspect_kernel(
    const float* __restrict__ aspect, const float* __restrict__ Wd, const float* __restrict__ bd,
    const float* __restrict__ wm, const float* __restrict__ bm)
{
    const int bh = blockIdx.x;
    const int b = bh >> 4;
    const int h = bh & 15;
    const int tid = threadIdx.x;

    __shared__ float asp_s[64];
    __shared__ float aw_s[64];

    {
        int e = tid >> 2, p = tid & 3;
        const float* av = aspect + (size_t)b * D + p * 256;
        const float* wv = Wd + (size_t)e * D + p * 256;
        float sum = 0.f;
#pragma unroll 4
        for (int d = 0; d < 256; d += 4) {
            float4 a = *(const float4*)(av + d);
            float4 w = *(const float4*)(wv + d);
            sum += a.x * w.x + a.y * w.y + a.z * w.z + a.w * w.w;
        }
        sum += __shfl_xor_sync(0xffffffffu, sum, 1, 4);
        sum += __shfl_xor_sync(0xffffffffu, sum, 2, 4);
        if (p == 0) asp_s[e] = sum + bd[e];
    }
    __syncthreads();
    if (tid < 64) {
        float s = 0.f;
        const float* w = wm + (size_t)h * DK * DK + tid;
#pragma unroll 8
        for (int c = 0; c < 64; c++) s += asp_s[c] * w[c * 64];
        aw_s[tid] = s;
    }
    __syncthreads();
    const float bias = bm[0];
    for (int j = tid; j < S; j += 256) {
        const __nv_bfloat162* kh =
            reinterpret_cast<const __nv_bfloat162*>(g_k_hi + ((size_t)b * S + j) * D + h * DK);
        const __nv_bfloat162* kl =
            reinterpret_cast<const __nv_bfloat162*>(g_k_lo + ((size_t)b * S + j) * D + h * DK);
        float s = 0.f;
#pragma unroll
        for (int d2 = 0; d2 < 32; d2++) {
            float2 a = __bfloat1622float2(kh[d2]);
            float2 c = __bfloat1622float2(kl[d2]);
            s += aw_s[2 * d2] * (a.x + c.x) + aw_s[2 * d2 + 1] * (a.y + c.y);
        }
        float x = s + bias;
        float t = 1.f - 2.f / (__expf(2.f * x) + 1.f);
        g_asco[(size_t)bh * S + j] = t;
    }
}

// ---------------------------------------------------------------------------
// Kernel 3: fused scores + softmax with split-bf16 mma.
// CTA: (b, h, 32 q-rows) x 1024 keys. 512 threads = 16 warps, warp = 32x64.
// ---------------------------------------------------------------------------
#define SC_SQHI 0
#define SC_SQLO 4608
#define SC_ASCS 9216
#define SC_REDM 13312
#define SC_REDS 15488
#define SC_REDM2 17664
#define SC_REDS2 17792
#define SC_SKHI 17920
#define SC_SKLO 99840
#define SC_TOTAL 181760

__global__ void __launch_bounds__(512, 1) scores_kernel(
    const float* __restrict__ shortp, const int* __restrict__ mask, float* __restrict__ out)
{
    extern __shared__ char smem_raw[];
    const int b = blockIdx.z;
    const int h = blockIdx.y;
    const int m0 = blockIdx.x * 32;
    const int bh = b * H + h;
    const int tid = threadIdx.x;
    const int lane = tid & 31;
    const int wid = tid >> 5;        // 0..15, warp col group: cols wid*64
    const unsigned sbase = sm_u32(smem_raw);

    // ---- load Q tile (32 rows x 64 dk, hi+lo) ----
    {
        int row = tid >> 4, g = tid & 15;                       // g: 4-bf16 group
        size_t goff = ((size_t)(b * S) + m0 + row) * D + h * DK + g * 4;
        *(uint2*)(smem_raw + SC_SQHI + row * 144 + g * 8) = *(const uint2*)(g_q_hi + goff);
        *(uint2*)(smem_raw + SC_SQLO + row * 144 + g * 8) = *(const uint2*)(g_q_lo + goff);
    }
    // ---- load aspect scores ----
    {
        ((float2*)(smem_raw + SC_ASCS))[tid] = *(const float2*)(g_asco + (size_t)bh * S + tid * 2);
    }

    float acc[2][8][4];
#pragma unroll
    for (int mt = 0; mt < 2; mt++)
#pragma unroll
        for (int nt = 0; nt < 8; nt++)
#pragma unroll
            for (int i = 0; i < 4; i++) acc[mt][nt][i] = 0.f;

    for (int chunk = 0; chunk < 2; chunk++) {
        if (chunk) __syncthreads();    // previous compute done before overwrite
        // ---- load K chunk: 1024 rows x 32 dk (hi+lo) ----
        // each row: 32 bf16 = 64 bytes = 4 x 16B groups -> 4096 stores by 512 thr
#pragma unroll
        for (int l = 0; l < 8; l++) {
            int f = tid + l * 512;                 // 0..4095
            int row = f >> 2, g = f & 3;           // g: which 16B (8 bf16)
            size_t goff = ((size_t)(b * S) + row) * D + h * DK + chunk * 32 + g * 8;
            *(uint4*)(smem_raw + SC_SKHI + row * 80 + g * 16) = *(const uint4*)(g_k_hi + goff);
            *(uint4*)(smem_raw + SC_SKLO + row * 80 + g * 16) = *(const uint4*)(g_k_lo + goff);
        }
        __syncthreads();

#pragma unroll
        for (int kk2 = 0; kk2 < 2; kk2++) {
            const int kglob = chunk * 2 + kk2;     // 0..3 (k16 step)
            unsigned ahi[2][4], alo[2][4];
#pragma unroll
            for (int mt = 0; mt < 2; mt++) {
                unsigned rbytes = (unsigned)(mt * 16 + (lane & 7) + ((lane >> 3) & 1) * 8) * 144
                                + ((lane >> 4) & 1) * 16 + kglob * 32;
                ldsm4(ahi[mt], sbase + SC_SQHI + rbytes);
                ldsm4(alo[mt], sbase + SC_SQLO + rbytes);
            }
#pragma unroll
            for (int nt2 = 0; nt2 < 4; nt2++) {
                unsigned rbytes = (unsigned)(wid * 64 + nt2 * 16 + (lane & 7) + ((lane >> 4) & 1) * 8) * 80
                                + ((lane >> 3) & 1) * 16 + kk2 * 32;
                unsigned bhi[4], blo[4];
                ldsm4(bhi, sbase + SC_SKHI + rbytes);
                ldsm4(blo, sbase + SC_SKLO + rbytes);
#pragma unroll
                for (int mt = 0; mt < 2; mt++) {
                    mma16816(acc[mt][nt2 * 2],     ahi[mt], bhi);
                    mma16816(acc[mt][nt2 * 2 + 1], ahi[mt], bhi + 2);
                    mma16816(acc[mt][nt2 * 2],     ahi[mt], blo);
                    mma16816(acc[mt][nt2 * 2 + 1], ahi[mt], blo + 2);
                    mma16816(acc[mt][nt2 * 2],     alo[mt], bhi);
                    mma16816(acc[mt][nt2 * 2 + 1], alo[mt], bhi + 2);
                }
            }
        }
    }

    // ---- fused epilogue: /8 + asco + short, mask, softmax over 1024 cols ----
    const int q = lane >> 2, tig = lane & 3;
    const float* ascf = (const float*)(smem_raw + SC_ASCS);
    float* redM = (float*)(smem_raw + SC_REDM);
    float* redS = (float*)(smem_raw + SC_REDS);
    float* redM2 = (float*)(smem_raw + SC_REDM2);
    float* redS2 = (float*)(smem_raw + SC_REDS2);

#pragma unroll
    for (int mt = 0; mt < 2; mt++) {
#pragma unroll
        for (int hf = 0; hf < 2; hf++) {
            int rl = mt * 16 + hf * 8 + q;
            int grow = m0 + rl;
            const float* shp = shortp + ((size_t)bh * S + grow) * S + wid * 64 + tig * 2;
            const int* mkp = mask + ((size_t)b * S + grow) * S + wid * 64 + tig * 2;
            float mx = -1e30f;
#pragma unroll
            for (int nt = 0; nt < 8; nt++) {
                float2 sh = *(const float2*)(shp + nt * 8);
                int2 mk = *(const int2*)(mkp + nt * 8);
                int ci = wid * 64 + nt * 8 + tig * 2;
                float s0 = acc[mt][nt][hf * 2]     * 0.125f + ascf[ci]     + sh.x;
                float s1 = acc[mt][nt][hf * 2 + 1] * 0.125f + ascf[ci + 1] + sh.y;
                s0 = mk.x ? s0 : -1e9f;
                s1 = mk.y ? s1 : -1e9f;
                acc[mt][nt][hf * 2] = s0;
                acc[mt][nt][hf * 2 + 1] = s1;
                mx = fmaxf(mx, fmaxf(s0, s1));
            }
            mx = fmaxf(mx, __shfl_xor_sync(0xffffffffu, mx, 1));
            mx = fmaxf(mx, __shfl_xor_sync(0xffffffffu, mx, 2));
            if (tig == 0) redM[rl * 17 + wid] = mx;
        }
    }
    __syncthreads();
    if (tid < 32) {
        float m = redM[tid * 17];
#pragma unroll
        for (int w = 1; w < 16; w++) m = fmaxf(m, redM[tid * 17 + w]);
        redM2[tid] = m;
    }
    __syncthreads();

#pragma unroll
    for (int mt = 0; mt < 2; mt++) {
#pragma unroll
        for (int hf = 0; hf < 2; hf++) {
            int rl = mt * 16 + hf * 8 + q;
            float m = redM2[rl];
            float sum = 0.f;
#pragma unroll
            for (int nt = 0; nt < 8; nt++) {
                float e0 = __expf(acc[mt][nt][hf * 2] - m);
                float e1 = __expf(acc[mt][nt][hf * 2 + 1] - m);
                acc[mt][nt][hf * 2] = e0;
                acc[mt][nt][hf * 2 + 1] = e1;
                sum += e0 + e1;
            }
            sum += __shfl_xor_sync(0xffffffffu, sum, 1);
            sum += __shfl_xor_sync(0xffffffffu, sum, 2);
            if (tig == 0) redS[rl * 17 + wid] = sum;
        }
    }
    __syncthreads();
    if (tid < 32) {
        float s = 0.f;
#pragma unroll
        for (int w = 0; w < 16; w++) s += redS[tid * 17 + w];
        redS2[tid] = s;
    }
    __syncthreads();

#pragma unroll
    for (int mt = 0; mt < 2; mt++) {
#pragma unroll
        for (int hf = 0; hf < 2; hf++) {
            int rl = mt * 16 + hf * 8 + q;
            int grow = m0 + rl;
            float inv = 1.0f / redS2[rl];
            float* op = out + ((size_t)bh * S + grow) * S + wid * 64 + tig * 2;
#pragma unroll
            for (int nt = 0; nt < 8; nt++) {
                float2 o;
                o.x = acc[mt][nt][hf * 2] * inv;
                o.y = acc[mt][nt][hf * 2 + 1] * inv;
                *(float2*)(op + nt * 8) = o;
            }
        }
    }
}

// ---------------------------------------------------------------------------
extern "C" void kernel_launch(void* const* d_in, const int* in_sizes, int n_in,
                              void* d_out, int out_size)
{
    const float* query  = (const float*)d_in[0];
    const float* key    = (const float*)d_in[1];
    const int*   mask   = (const int*)  d_in[2];
    const float* aspect = (const float*)d_in[3];
    const float* shortp = (const float*)d_in[4];
    const float* Wq     = (const float*)d_in[5];
    const float* bq     = (const float*)d_in[6];
    const float* Wk     = (const float*)d_in[7];
    const float* bk     = (const float*)d_in[8];
    const float* Wd     = (const float*)d_in[9];
    const float* bd     = (const float*)d_in[10];
    const float* wm     = (const float*)d_in[11];
    const float* bm     = (const float*)d_in[12];
    float* out = (float*)d_out;

    cudaFuncSetAttribute(proj_kernel, cudaFuncAttributeMaxDynamicSharedMemorySize, 2 * PJ_BUF);
    cudaFuncSetAttribute(scores_kernel, cudaFuncAttributeMaxDynamicSharedMemorySize, SC_TOTAL);

    dim3 gp(32, 8, 2);                   // M tiles, N tiles, {Q,K}
    proj_kernel<<<gp, 256, 2 * PJ_BUF>>>(query, Wq, bq, key, Wk, bk);

    aspect_kernel<<<BATCH * H, 256>>>(aspect, Wd, bd, wm, bm);

    dim3 gs(S / 32, H, BATCH);
    scores_kernel<<<gs, 512, SC_TOTAL>>>(shortp, mask, out);
}